// round 13
// baseline (speedup 1.0000x reference)
#include <cuda_runtime.h>
#include <cuda_fp16.h>
#include <cstdint>

namespace {

constexpr int H = 128, W = 128, D = 128;
constexpr int N = H * W * D;          // 2^21
constexpr int B = 2;

// brick / tile geometry
constexpr int BX = 16, BY = 16, BZ = 32;        // voxels per block (8192)
constexpr int HX = 7, HY = 6, HZ = 8;           // halos (z halo 8-aligned)
constexpr int TX = BX + 2 * HX + 1;             // 31
constexpr int TY = BY + 2 * HY + 1;             // 29
constexpr int TZ = 56;                          // 49 needed; mult of 8 => 16B rows
constexpr int NROWS = TX * TY;                  // 899
constexpr int TILE_BYTES = NROWS * TZ * 2;      // 100,688
constexpr int DDF_FLOATS = 3 * 16 * 32;         // 1536 floats per slab buffer
constexpr int SMEM_BYTES = TILE_BYTES + 2 * DDF_FLOATS * 4;  // 112,976 (x2 < 228KB)

// fp16 copy of the image (staging reads + rare fallback gathers)
__device__ __align__(16) __half g_img16[(size_t)B * N];

// ---------------- prepass: fp32 image -> fp16 copy ----------------
__global__ __launch_bounds__(256) void pack16_kernel(const float* __restrict__ img) {
    int t = blockIdx.x * blockDim.x + threadIdx.x;
    int base = t * 8;
    float4 a = *reinterpret_cast<const float4*>(img + base);
    float4 c = *reinterpret_cast<const float4*>(img + base + 4);
    __half2 h[4];
    h[0] = __floats2half2_rn(a.x, a.y);
    h[1] = __floats2half2_rn(a.z, a.w);
    h[2] = __floats2half2_rn(c.x, c.y);
    h[3] = __floats2half2_rn(c.z, c.w);
    *reinterpret_cast<uint4*>(g_img16 + base) = *reinterpret_cast<uint4*>(h);
}

// rare fallback: fully masked trilinear gather from global fp16 image
__device__ __noinline__ float sample_masked(const __half* __restrict__ img,
                                            float tx, float ty, float tz,
                                            int x0, int y0, int z0) {
    int x1 = x0 + 1, y1 = y0 + 1, z1 = z0 + 1;
    float wx0 = ((unsigned)x0 < (unsigned)H) ? (1.0f - tx) : 0.0f;
    float wx1 = ((unsigned)x1 < (unsigned)H) ? tx          : 0.0f;
    float wy0 = ((unsigned)y0 < (unsigned)W) ? (1.0f - ty) : 0.0f;
    float wy1 = ((unsigned)y1 < (unsigned)W) ? ty          : 0.0f;
    float wz0 = ((unsigned)z0 < (unsigned)D) ? (1.0f - tz) : 0.0f;
    float wz1 = ((unsigned)z1 < (unsigned)D) ? tz          : 0.0f;
    int cx0 = min(max(x0, 0), H - 1), cx1 = min(max(x1, 0), H - 1);
    int cy0 = min(max(y0, 0), W - 1), cy1 = min(max(y1, 0), W - 1);
    int cz0 = min(max(z0, 0), D - 1), cz1 = min(max(z1, 0), D - 1);
    int bx0 = cx0 * (W * D), bx1 = cx1 * (W * D);
    int by0 = cy0 * D,       by1 = cy1 * D;
    float v000 = __half2float(__ldg(img + bx0 + by0 + cz0));
    float v001 = __half2float(__ldg(img + bx0 + by0 + cz1));
    float v010 = __half2float(__ldg(img + bx0 + by1 + cz0));
    float v011 = __half2float(__ldg(img + bx0 + by1 + cz1));
    float v100 = __half2float(__ldg(img + bx1 + by0 + cz0));
    float v101 = __half2float(__ldg(img + bx1 + by0 + cz1));
    float v110 = __half2float(__ldg(img + bx1 + by1 + cz0));
    float v111 = __half2float(__ldg(img + bx1 + by1 + cz1));
    float c00 = fmaf(wz0, v000, wz1 * v001);
    float c01 = fmaf(wz0, v010, wz1 * v011);
    float c10 = fmaf(wz0, v100, wz1 * v101);
    float c11 = fmaf(wz0, v110, wz1 * v111);
    float d0 = fmaf(wy0, c00, wy1 * c01);
    float d1 = fmaf(wy0, c10, wy1 * c11);
    return fmaf(wx0, d0, wx1 * d1);
}

__device__ __forceinline__ void cp16(unsigned int smem_addr, const void* gptr, int src_bytes) {
    asm volatile("cp.async.cg.shared.global [%0], [%1], 16, %2;\n"
                 :: "r"(smem_addr), "l"(gptr), "r"(src_bytes));
}

// ---------------- main kernel: one 16x16x32 brick per 512-thread block ----------------
__global__ __launch_bounds__(512, 2) void warp_kernel(const float* __restrict__ ddf,
                                                      float* __restrict__ out) {
    extern __shared__ char smem_raw[];
    __half* tile = reinterpret_cast<__half*>(smem_raw);          // [31][29][56]
    float* dsm = reinterpret_cast<float*>(smem_raw + TILE_BYTES); // [2][3][16][32]

    int bid = blockIdx.x;
    int bz = bid & 3;
    int by = (bid >> 2) & 7;
    int bx = (bid >> 5) & 7;
    int b  = bid >> 8;

    int X0 = bx * BX, Y0 = by * BY, Z0 = bz * BZ;
    int gx0 = X0 - HX, gy0 = Y0 - HY, gz0 = Z0 - HZ;   // gz0 multiple of 8

    const __half* img = g_img16 + (size_t)b * N;
    const float* dbase0 = ddf + (size_t)b * 3 * N;
    int tid = threadIdx.x;
    int warp = tid >> 5, lane = tid & 31;
    unsigned int tbase = (unsigned int)__cvta_generic_to_shared(smem_raw);

    // ---- group 0: image tile via cp.async (7 x 16B chunks per 112B row) ----
    {
        int lrow = lane / 7;            // 0..4
        int lchk = lane - lrow * 7;     // 0..6
        bool lactive = lane < 28;
        int zoff = lchk * 8;
        int gzc = gz0 + zoff;           // 8-aligned chunk start
        bool zok = (unsigned)gzc < (unsigned)D;

        #pragma unroll 1
        for (int rb = warp * 4; rb < NROWS; rb += 16 * 4) {
            int row = rb + lrow;
            if (lactive && row < NROWS) {
                unsigned i = (unsigned)row / (unsigned)TY;
                unsigned j = (unsigned)row - i * TY;
                int gx = gx0 + (int)i, gy = gy0 + (int)j;
                bool ok = ((unsigned)gx < (unsigned)H) & ((unsigned)gy < (unsigned)W) & zok;
                int cgx = min(max(gx, 0), H - 1), cgy = min(max(gy, 0), W - 1);
                const void* src = img + (((cgx << 7) | cgy) << 7) + (ok ? gzc : 0);
                unsigned int dst = tbase + (unsigned int)(row * TZ + zoff) * 2u;
                cp16(dst, src, ok ? 16 : 0);   // src_bytes=0 -> zero-fill (padding)
            }
        }
        asm volatile("cp.async.commit_group;\n");
    }

    // ---- ddf slab staging: slab s = x-plane X0+s (16 y x 32 z x 3 comp = 6KB) ----
    auto stage_slab = [&](int s, int buf) {
        if (tid < 384) {
            int comp = tid >> 7;            // 0..2
            int rest = tid & 127;
            int yy = rest >> 3;             // 0..15
            int zc = rest & 7;              // 0..7 (4-float chunks)
            const float* src = dbase0 + comp * N +
                               ((((X0 + s) << 7) | (Y0 + yy)) << 7) + Z0 + zc * 4;
            unsigned int dst = tbase + TILE_BYTES +
                               (unsigned int)(buf * DDF_FLOATS + comp * 512 + yy * 32 + zc * 4) * 4u;
            cp16(dst, src, 16);
        }
    };

    stage_slab(0, 0);
    asm volatile("cp.async.commit_group;\n");   // group 1
    stage_slab(1, 1);
    asm volatile("cp.async.commit_group;\n");   // group 2

    // ---- compute: 16 x-slabs, depth-2 ddf pipeline ----
    float* outb = out + (size_t)b * N;
    int y = Y0 + warp, z = Z0 + lane;
    int rcur = ((X0 << 7 | y) << 7) | z;
    constexpr int RSTEP = 1 << 14;

    #pragma unroll 1
    for (int it = 0; it < 16; it++) {
        asm volatile("cp.async.wait_group 1;\n");   // all but newest group done
        __syncthreads();                            // slab `it` visible to all

        int bufo = (it & 1) * DDF_FLOATS + warp * 32 + lane;
        float cdx = dsm[bufo];
        float cdy = dsm[bufo + 512];
        float cdz = dsm[bufo + 1024];

        int x = X0 + it;
        float fx = (float)x + cdx;
        float fy = (float)y + cdy;
        float fz = (float)z + cdz;

        float x0f = floorf(fx), y0f = floorf(fy), z0f = floorf(fz);
        float tx = fx - x0f, ty = fy - y0f, tz = fz - z0f;
        int x0 = (int)x0f, y0 = (int)y0f, z0 = (int)z0f;

        int x0l = x0 - gx0, y0l = y0 - gy0, z0l = z0 - gz0;
        bool bad = ((unsigned)x0l > (unsigned)(TX - 2)) |
                   ((unsigned)y0l > (unsigned)(TY - 2)) |
                   ((unsigned)z0l > (unsigned)(TZ - 2));

        float res;
        if (!bad) {
            // zeros-padding baked into the staged tile: unmasked 8-tap trilerp
            int base = (x0l * TY + y0l) * TZ + z0l;
            float v000 = __half2float(tile[base]);
            float v001 = __half2float(tile[base + 1]);
            float v010 = __half2float(tile[base + TZ]);
            float v011 = __half2float(tile[base + TZ + 1]);
            float v100 = __half2float(tile[base + TY * TZ]);
            float v101 = __half2float(tile[base + TY * TZ + 1]);
            float v110 = __half2float(tile[base + TY * TZ + TZ]);
            float v111 = __half2float(tile[base + TY * TZ + TZ + 1]);
            float c00 = fmaf(1.0f - tz, v000, tz * v001);
            float c01 = fmaf(1.0f - tz, v010, tz * v011);
            float c10 = fmaf(1.0f - tz, v100, tz * v101);
            float c11 = fmaf(1.0f - tz, v110, tz * v111);
            float d0 = fmaf(1.0f - ty, c00, ty * c01);
            float d1 = fmaf(1.0f - ty, c10, ty * c11);
            res = fmaf(1.0f - tx, d0, tx * d1);
        } else {
            res = sample_masked(img, tx, ty, tz, x0, y0, z0);
        }
        outb[rcur] = res;
        rcur += RSTEP;

        __syncthreads();                 // all warps done reading dsm buf (it&1)
        if (it < 14) stage_slab(it + 2, it & 1);
        asm volatile("cp.async.commit_group;\n");   // uniform group count per iter
    }
}

} // namespace

extern "C" void kernel_launch(void* const* d_in, const int* in_sizes, int n_in,
                              void* d_out, int out_size) {
    const float* image = (const float*)d_in[0];  // (B, 1, H, W, D) fp32
    const float* ddf   = (const float*)d_in[1];  // (B, 3, H, W, D) fp32
    float* out         = (float*)d_out;          // (B, 1, H, W, D) fp32

    static bool attr_set = false;
    if (!attr_set) {
        cudaFuncSetAttribute(warp_kernel, cudaFuncAttributeMaxDynamicSharedMemorySize,
                             SMEM_BYTES);
        attr_set = true;
    }

    int pack_threads = (B * N) / 8;              // 524,288
    pack16_kernel<<<pack_threads / 256, 256>>>(image);

    int bricks = B * (H / BX) * (W / BY) * (D / BZ);   // 512
    warp_kernel<<<bricks, 512, SMEM_BYTES>>>(ddf, out);
}

// round 14
// speedup vs baseline: 1.0812x; 1.0812x over previous
#include <cuda_runtime.h>
#include <cuda_fp16.h>
#include <cstdint>

namespace {

constexpr int H = 128, W = 128, D = 128;
constexpr int N = H * W * D;          // 2^21
constexpr int B = 2;

// brick / tile geometry: one big brick per 1024-thread CTA
constexpr int BX = 16, BY = 16, BZ = 64;        // voxels per block (16384)
constexpr int HXY = 8;                          // x/y halo
constexpr int HZ = 16;                          // z halo (16-aligned)
constexpr int TX = BX + 2 * HXY + 1;            // 33
constexpr int TY = BY + 2 * HXY + 1;            // 33
constexpr int TZ = 104;                         // 97 needed; pad to mult of 8
constexpr int NROWS = TX * TY;                  // 1089
constexpr int SMEM_BYTES = NROWS * TZ * 2;      // 226,512 (< 227KB max dyn smem)

// fp16 copy of the image (staging reads + rare fallback gathers)
__device__ __align__(16) __half g_img16[(size_t)B * N];

// ---------------- prepass: fp32 image -> fp16 copy ----------------
__global__ __launch_bounds__(256) void pack16_kernel(const float* __restrict__ img) {
    int t = blockIdx.x * blockDim.x + threadIdx.x;
    int base = t * 8;
    float4 a = *reinterpret_cast<const float4*>(img + base);
    float4 c = *reinterpret_cast<const float4*>(img + base + 4);
    __half2 h[4];
    h[0] = __floats2half2_rn(a.x, a.y);
    h[1] = __floats2half2_rn(a.z, a.w);
    h[2] = __floats2half2_rn(c.x, c.y);
    h[3] = __floats2half2_rn(c.z, c.w);
    *reinterpret_cast<uint4*>(g_img16 + base) = *reinterpret_cast<uint4*>(h);
}

// rare fallback: fully masked trilinear gather from global fp16 image
__device__ __noinline__ float sample_masked(const __half* __restrict__ img,
                                            float tx, float ty, float tz,
                                            int x0, int y0, int z0) {
    int x1 = x0 + 1, y1 = y0 + 1, z1 = z0 + 1;
    float wx0 = ((unsigned)x0 < (unsigned)H) ? (1.0f - tx) : 0.0f;
    float wx1 = ((unsigned)x1 < (unsigned)H) ? tx          : 0.0f;
    float wy0 = ((unsigned)y0 < (unsigned)W) ? (1.0f - ty) : 0.0f;
    float wy1 = ((unsigned)y1 < (unsigned)W) ? ty          : 0.0f;
    float wz0 = ((unsigned)z0 < (unsigned)D) ? (1.0f - tz) : 0.0f;
    float wz1 = ((unsigned)z1 < (unsigned)D) ? tz          : 0.0f;
    int cx0 = min(max(x0, 0), H - 1), cx1 = min(max(x1, 0), H - 1);
    int cy0 = min(max(y0, 0), W - 1), cy1 = min(max(y1, 0), W - 1);
    int cz0 = min(max(z0, 0), D - 1), cz1 = min(max(z1, 0), D - 1);
    int bx0 = cx0 * (W * D), bx1 = cx1 * (W * D);
    int by0 = cy0 * D,       by1 = cy1 * D;
    float v000 = __half2float(__ldg(img + bx0 + by0 + cz0));
    float v001 = __half2float(__ldg(img + bx0 + by0 + cz1));
    float v010 = __half2float(__ldg(img + bx0 + by1 + cz0));
    float v011 = __half2float(__ldg(img + bx0 + by1 + cz1));
    float v100 = __half2float(__ldg(img + bx1 + by0 + cz0));
    float v101 = __half2float(__ldg(img + bx1 + by0 + cz1));
    float v110 = __half2float(__ldg(img + bx1 + by1 + cz0));
    float v111 = __half2float(__ldg(img + bx1 + by1 + cz1));
    float c00 = fmaf(wz0, v000, wz1 * v001);
    float c01 = fmaf(wz0, v010, wz1 * v011);
    float c10 = fmaf(wz0, v100, wz1 * v101);
    float c11 = fmaf(wz0, v110, wz1 * v111);
    float d0 = fmaf(wy0, c00, wy1 * c01);
    float d1 = fmaf(wy0, c10, wy1 * c11);
    return fmaf(wx0, d0, wx1 * d1);
}

__device__ __forceinline__ void cp16(unsigned int smem_addr, const void* gptr, int src_bytes) {
    asm volatile("cp.async.cg.shared.global [%0], [%1], 16, %2;\n"
                 :: "r"(smem_addr), "l"(gptr), "r"(src_bytes));
}

// ---------------- main kernel: one 16x16x64 brick per 1024-thread block ----------------
__global__ __launch_bounds__(1024, 1) void warp_kernel(const float* __restrict__ ddf,
                                                       float* __restrict__ out) {
    extern __shared__ __half tile[];   // [TX=33][TY=33][TZ=104]

    int bid = blockIdx.x;
    int bz = bid & 1;
    int by = (bid >> 1) & 7;
    int bx = (bid >> 4) & 7;
    int b  = bid >> 7;

    int X0 = bx * BX, Y0 = by * BY, Z0 = bz * BZ;
    int gx0 = X0 - HXY, gy0 = Y0 - HXY, gz0 = Z0 - HZ;   // gz0 multiple of 16

    const __half* img = g_img16 + (size_t)b * N;
    int tid = threadIdx.x;
    int warp = tid >> 5, lane = tid & 31;

    // ---- stage via cp.async: 2 rows per warp-iter, 13 x 16B chunks per 208B row ----
    // gz0 16-aligned => every 16B chunk entirely inside or outside the volume;
    // src_bytes=0 zero-fills => zeros-padding baked into the tile.
    {
        int lrow = lane / 13;           // 0..1 active (lanes 26..31 idle)
        int lchk = lane - lrow * 13;    // 0..12
        bool lactive = lane < 26;
        int zoff = lchk * 8;            // half offset within row
        int gzc = gz0 + zoff;           // chunk global z start (8-aligned)
        bool zok = (unsigned)gzc < (unsigned)D;
        unsigned int tbase = (unsigned int)__cvta_generic_to_shared(tile);

        #pragma unroll 1
        for (int rb = warp * 2; rb < NROWS; rb += 32 * 2) {
            int row = rb + lrow;
            if (lactive && row < NROWS) {
                unsigned i = (unsigned)row / (unsigned)TY;
                unsigned j = (unsigned)row - i * TY;
                int gx = gx0 + (int)i, gy = gy0 + (int)j;
                bool ok = ((unsigned)gx < (unsigned)H) & ((unsigned)gy < (unsigned)W) & zok;
                int cgx = min(max(gx, 0), H - 1), cgy = min(max(gy, 0), W - 1);
                const void* src = img + (((cgx << 7) | cgy) << 7) + (ok ? gzc : 0);
                unsigned int dst = tbase + (unsigned int)(row * TZ + zoff) * 2u;
                cp16(dst, src, ok ? 16 : 0);
            }
        }
        asm volatile("cp.async.commit_group;\n");
        asm volatile("cp.async.wait_group 0;\n");
    }
    __syncthreads();
    // no further barriers: warps proceed independently

    // ---- compute: warp = (xl, z-half); 16 iters over y, constant strides ----
    const float* dbase0 = ddf + (size_t)b * 3 * N;
    float* outb = out + (size_t)b * N;

    int xl = warp >> 1, zh = warp & 1;
    int x = X0 + xl;
    int z = Z0 + zh * 32 + lane;
    int rcur = ((x << 7 | Y0) << 7) | z;
    constexpr int RSTEP = 1 << 7;                      // y += 1 per iteration

    const float* pd = dbase0 + rcur;
    float dx = __ldg(pd), dy = __ldg(pd + N), dz = __ldg(pd + 2 * N);

    int y = Y0;

    #pragma unroll
    for (int it = 0; it < 16; it++) {
        float cdx = dx, cdy = dy, cdz = dz;
        if (it < 15) {                                  // prefetch next iteration
            pd += RSTEP;
            dx = __ldg(pd); dy = __ldg(pd + N); dz = __ldg(pd + 2 * N);
        }

        float fx = (float)x + cdx;
        float fy = (float)y + cdy;
        float fz = (float)z + cdz;

        float x0f = floorf(fx), y0f = floorf(fy), z0f = floorf(fz);
        float tx = fx - x0f, ty = fy - y0f, tz = fz - z0f;
        int x0 = (int)x0f, y0 = (int)y0f, z0 = (int)z0f;

        int x0l = x0 - gx0, y0l = y0 - gy0, z0l = z0 - gz0;
        bool bad = ((unsigned)x0l > (unsigned)(TX - 2)) |
                   ((unsigned)y0l > (unsigned)(TY - 2)) |
                   ((unsigned)z0l > (unsigned)(TZ - 2));

        float res;
        if (!bad) {
            // zeros-padding baked into the staged tile: unmasked 8-tap trilerp
            int base = (x0l * TY + y0l) * TZ + z0l;
            float v000 = __half2float(tile[base]);
            float v001 = __half2float(tile[base + 1]);
            float v010 = __half2float(tile[base + TZ]);
            float v011 = __half2float(tile[base + TZ + 1]);
            float v100 = __half2float(tile[base + TY * TZ]);
            float v101 = __half2float(tile[base + TY * TZ + 1]);
            float v110 = __half2float(tile[base + TY * TZ + TZ]);
            float v111 = __half2float(tile[base + TY * TZ + TZ + 1]);
            float c00 = fmaf(1.0f - tz, v000, tz * v001);
            float c01 = fmaf(1.0f - tz, v010, tz * v011);
            float c10 = fmaf(1.0f - tz, v100, tz * v101);
            float c11 = fmaf(1.0f - tz, v110, tz * v111);
            float d0 = fmaf(1.0f - ty, c00, ty * c01);
            float d1 = fmaf(1.0f - ty, c10, ty * c11);
            res = fmaf(1.0f - tx, d0, tx * d1);
        } else {
            res = sample_masked(img, tx, ty, tz, x0, y0, z0);
        }
        outb[rcur] = res;
        rcur += RSTEP;
        y += 1;
    }
}

} // namespace

extern "C" void kernel_launch(void* const* d_in, const int* in_sizes, int n_in,
                              void* d_out, int out_size) {
    const float* image = (const float*)d_in[0];  // (B, 1, H, W, D) fp32
    const float* ddf   = (const float*)d_in[1];  // (B, 3, H, W, D) fp32
    float* out         = (float*)d_out;          // (B, 1, H, W, D) fp32

    static bool attr_set = false;
    if (!attr_set) {
        cudaFuncSetAttribute(warp_kernel, cudaFuncAttributeMaxDynamicSharedMemorySize,
                             SMEM_BYTES);
        attr_set = true;
    }

    int pack_threads = (B * N) / 8;              // 524,288
    pack16_kernel<<<pack_threads / 256, 256>>>(image);

    int bricks = B * (H / BX) * (W / BY) * (D / BZ);   // 256
    warp_kernel<<<bricks, 1024, SMEM_BYTES>>>(ddf, out);
}

// round 16
// speedup vs baseline: 1.1568x; 1.0699x over previous
#include <cuda_runtime.h>
#include <cuda_fp16.h>
#include <cstdint>

namespace {

constexpr int H = 128, W = 128, D = 128;
constexpr int N = H * W * D;          // 2^21
constexpr int B = 2;

// brick / tile geometry: one big brick per 1024-thread CTA
constexpr int BX = 16, BY = 16, BZ = 64;        // voxels per block (16384)
constexpr int HXY = 8;                          // x/y halo
constexpr int HZ = 16;                          // z halo (16-aligned)
constexpr int TX = BX + 2 * HXY + 1;            // 33
constexpr int TY = BY + 2 * HXY + 1;            // 33
constexpr int TZ = 104;                         // 97 needed; 208B rows (16B mult)
constexpr int NROWS = TX * TY;                  // 1089
constexpr int TILE_BYTES = NROWS * TZ * 2;      // 226,512
constexpr int SMEM_BYTES = TILE_BYTES + 16;     // + mbarrier

// fp16 copy of the image (staging reads + rare fallback gathers)
__device__ __align__(16) __half g_img16[(size_t)B * N];

// ---------------- prepass: fp32 image -> fp16 copy ----------------
__global__ __launch_bounds__(256) void pack16_kernel(const float* __restrict__ img) {
    int t = blockIdx.x * blockDim.x + threadIdx.x;
    int base = t * 8;
    float4 a = *reinterpret_cast<const float4*>(img + base);
    float4 c = *reinterpret_cast<const float4*>(img + base + 4);
    __half2 h[4];
    h[0] = __floats2half2_rn(a.x, a.y);
    h[1] = __floats2half2_rn(a.z, a.w);
    h[2] = __floats2half2_rn(c.x, c.y);
    h[3] = __floats2half2_rn(c.z, c.w);
    *reinterpret_cast<uint4*>(g_img16 + base) = *reinterpret_cast<uint4*>(h);
}

// rare fallback: fully masked trilinear gather from global fp16 image
__device__ __noinline__ float sample_masked(const __half* __restrict__ img,
                                            float tx, float ty, float tz,
                                            int x0, int y0, int z0) {
    int x1 = x0 + 1, y1 = y0 + 1, z1 = z0 + 1;
    float wx0 = ((unsigned)x0 < (unsigned)H) ? (1.0f - tx) : 0.0f;
    float wx1 = ((unsigned)x1 < (unsigned)H) ? tx          : 0.0f;
    float wy0 = ((unsigned)y0 < (unsigned)W) ? (1.0f - ty) : 0.0f;
    float wy1 = ((unsigned)y1 < (unsigned)W) ? ty          : 0.0f;
    float wz0 = ((unsigned)z0 < (unsigned)D) ? (1.0f - tz) : 0.0f;
    float wz1 = ((unsigned)z1 < (unsigned)D) ? tz          : 0.0f;
    int cx0 = min(max(x0, 0), H - 1), cx1 = min(max(x1, 0), H - 1);
    int cy0 = min(max(y0, 0), W - 1), cy1 = min(max(y1, 0), W - 1);
    int cz0 = min(max(z0, 0), D - 1), cz1 = min(max(z1, 0), D - 1);
    int bx0 = cx0 * (W * D), bx1 = cx1 * (W * D);
    int by0 = cy0 * D,       by1 = cy1 * D;
    float v000 = __half2float(__ldg(img + bx0 + by0 + cz0));
    float v001 = __half2float(__ldg(img + bx0 + by0 + cz1));
    float v010 = __half2float(__ldg(img + bx0 + by1 + cz0));
    float v011 = __half2float(__ldg(img + bx0 + by1 + cz1));
    float v100 = __half2float(__ldg(img + bx1 + by0 + cz0));
    float v101 = __half2float(__ldg(img + bx1 + by0 + cz1));
    float v110 = __half2float(__ldg(img + bx1 + by1 + cz0));
    float v111 = __half2float(__ldg(img + bx1 + by1 + cz1));
    float c00 = fmaf(wz0, v000, wz1 * v001);
    float c01 = fmaf(wz0, v010, wz1 * v011);
    float c10 = fmaf(wz0, v100, wz1 * v101);
    float c11 = fmaf(wz0, v110, wz1 * v111);
    float d0 = fmaf(wy0, c00, wy1 * c01);
    float d1 = fmaf(wy0, c10, wy1 * c11);
    return fmaf(wx0, d0, wx1 * d1);
}

__device__ __forceinline__ void bulk_cp(unsigned int dst_smem, const void* src,
                                        unsigned int bytes, unsigned int mbar) {
    asm volatile(
        "cp.async.bulk.shared::cluster.global.mbarrier::complete_tx::bytes "
        "[%0], [%1], %2, [%3];\n"
        :: "r"(dst_smem), "l"(src), "r"(bytes), "r"(mbar) : "memory");
}

// ---------------- main kernel: one 16x16x64 brick per 1024-thread block ----------------
__global__ __launch_bounds__(1024, 1) void warp_kernel(const float* __restrict__ ddf,
                                                       float* __restrict__ out) {
    extern __shared__ __half tile[];   // [TX=33][TY=33][TZ=104], mbarrier after

    int bid = blockIdx.x;
    int bz = bid & 1;
    int by = (bid >> 1) & 7;
    int bx = (bid >> 4) & 7;
    int b  = bid >> 7;

    int X0 = bx * BX, Y0 = by * BY, Z0 = bz * BZ;
    int gx0 = X0 - HXY, gy0 = Y0 - HXY, gz0 = Z0 - HZ;   // gz0 multiple of 16

    const __half* img = g_img16 + (size_t)b * N;
    int tid = threadIdx.x;
    int warp = tid >> 5, lane = tid & 31;

    unsigned int tbase = (unsigned int)__cvta_generic_to_shared(tile);
    unsigned int mbar = tbase + (unsigned int)TILE_BYTES;

    // in-bounds z range for every row (gz0, bounds all multiples of 16)
    int zlo = max(gz0, 0), zhi = min(gz0 + TZ, D);
    int zbytes = (zhi - zlo) * 2;                       // multiple of 16
    int zdst0 = (zlo - gz0) * 2;                        // front pad bytes (mult of 16)

    // ---- init mbarrier + expect_tx (thread 0) ----
    if (tid == 0) {
        asm volatile("mbarrier.init.shared.b64 [%0], %1;" :: "r"(mbar), "r"(1u) : "memory");
    }
    __syncthreads();
    if (tid == 0) {
        int ilo = max(0, -gx0), ihi = min(TX, H - gx0);
        int jlo = max(0, -gy0), jhi = min(TY, W - gy0);
        unsigned int tx_total = (unsigned int)((ihi - ilo) * (jhi - jlo)) * (unsigned int)zbytes;
        asm volatile("mbarrier.arrive.expect_tx.shared.b64 _, [%0], %1;"
                     :: "r"(mbar), "r"(tx_total) : "memory");
    }
    __syncthreads();

    // ---- stage: one bulk copy per valid (x,y) row; zero-fill pads / OOB rows ----
    {
        const uint4 zero4 = make_uint4(0, 0, 0, 0);
        #pragma unroll
        for (int pass = 0; pass < 2; pass++) {
            int row = tid + pass * 1024;
            if (row < NROWS) {
                unsigned i = (unsigned)row / (unsigned)TY;
                unsigned j = (unsigned)row - i * TY;
                int gx = gx0 + (int)i, gy = gy0 + (int)j;
                unsigned int drow = tbase + (unsigned int)(row * TZ) * 2u;
                uint4* drow_g = reinterpret_cast<uint4*>(tile + row * TZ);
                if (((unsigned)gx < (unsigned)H) & ((unsigned)gy < (unsigned)W)) {
                    const void* src = img + (((gx << 7) | gy) << 7) + zlo;
                    bulk_cp(drow + (unsigned int)zdst0, src, (unsigned int)zbytes, mbar);
                    // zero the z pads (front: zdst0 bytes; back: after zdst0+zbytes)
                    for (int o = 0; o < zdst0; o += 16) drow_g[o >> 4] = zero4;
                    for (int o = zdst0 + zbytes; o < TZ * 2; o += 16) drow_g[o >> 4] = zero4;
                } else {
                    #pragma unroll
                    for (int o = 0; o < TZ * 2 / 16; o++) drow_g[o] = zero4;
                }
            }
        }
    }

    // ---- wait for all bulk copies (tx-count) ----
    {
        unsigned int done = 0;
        while (!done) {
            asm volatile(
                "{\n\t.reg .pred P1;\n\t"
                "mbarrier.try_wait.parity.shared.b64 P1, [%1], %2, 0x989680;\n\t"
                "selp.b32 %0, 1, 0, P1;\n\t}"
                : "=r"(done) : "r"(mbar), "r"(0u) : "memory");
        }
    }
    __syncthreads();
    // no further barriers: warps proceed independently

    // ---- compute: warp = (xl, z-half); 16 iters over y, constant strides ----
    const float* dbase0 = ddf + (size_t)b * 3 * N;
    float* outb = out + (size_t)b * N;

    int xl = warp >> 1, zh = warp & 1;
    int x = X0 + xl;
    int z = Z0 + zh * 32 + lane;
    int rcur = ((x << 7 | Y0) << 7) | z;
    constexpr int RSTEP = 1 << 7;                      // y += 1 per iteration

    const float* pd = dbase0 + rcur;
    float dx = __ldg(pd), dy = __ldg(pd + N), dz = __ldg(pd + 2 * N);

    int y = Y0;

    #pragma unroll
    for (int it = 0; it < 16; it++) {
        float cdx = dx, cdy = dy, cdz = dz;
        if (it < 15) {                                  // prefetch next iteration
            pd += RSTEP;
            dx = __ldg(pd); dy = __ldg(pd + N); dz = __ldg(pd + 2 * N);
        }

        float fx = (float)x + cdx;
        float fy = (float)y + cdy;
        float fz = (float)z + cdz;

        float x0f = floorf(fx), y0f = floorf(fy), z0f = floorf(fz);
        float tx = fx - x0f, ty = fy - y0f, tz = fz - z0f;
        int x0 = (int)x0f, y0 = (int)y0f, z0 = (int)z0f;

        int x0l = x0 - gx0, y0l = y0 - gy0, z0l = z0 - gz0;
        bool bad = ((unsigned)x0l > (unsigned)(TX - 2)) |
                   ((unsigned)y0l > (unsigned)(TY - 2)) |
                   ((unsigned)z0l > (unsigned)(TZ - 2));

        float res;
        if (!bad) {
            // zeros-padding baked into the staged tile: unmasked 8-tap trilerp
            int base = (x0l * TY + y0l) * TZ + z0l;
            float v000 = __half2float(tile[base]);
            float v001 = __half2float(tile[base + 1]);
            float v010 = __half2float(tile[base + TZ]);
            float v011 = __half2float(tile[base + TZ + 1]);
            float v100 = __half2float(tile[base + TY * TZ]);
            float v101 = __half2float(tile[base + TY * TZ + 1]);
            float v110 = __half2float(tile[base + TY * TZ + TZ]);
            float v111 = __half2float(tile[base + TY * TZ + TZ + 1]);
            float c00 = fmaf(1.0f - tz, v000, tz * v001);
            float c01 = fmaf(1.0f - tz, v010, tz * v011);
            float c10 = fmaf(1.0f - tz, v100, tz * v101);
            float c11 = fmaf(1.0f - tz, v110, tz * v111);
            float d0 = fmaf(1.0f - ty, c00, ty * c01);
            float d1 = fmaf(1.0f - ty, c10, ty * c11);
            res = fmaf(1.0f - tx, d0, tx * d1);
        } else {
            res = sample_masked(img, tx, ty, tz, x0, y0, z0);
        }
        outb[rcur] = res;
        rcur += RSTEP;
        y += 1;
    }
}

} // namespace

extern "C" void kernel_launch(void* const* d_in, const int* in_sizes, int n_in,
                              void* d_out, int out_size) {
    const float* image = (const float*)d_in[0];  // (B, 1, H, W, D) fp32
    const float* ddf   = (const float*)d_in[1];  // (B, 3, H, W, D) fp32
    float* out         = (float*)d_out;          // (B, 1, H, W, D) fp32

    static bool attr_set = false;
    if (!attr_set) {
        cudaFuncSetAttribute(warp_kernel, cudaFuncAttributeMaxDynamicSharedMemorySize,
                             SMEM_BYTES);
        attr_set = true;
    }

    int pack_threads = (B * N) / 8;              // 524,288
    pack16_kernel<<<pack_threads / 256, 256>>>(image);

    int bricks = B * (H / BX) * (W / BY) * (D / BZ);   // 256
    warp_kernel<<<bricks, 1024, SMEM_BYTES>>>(ddf, out);
}

// round 17
// speedup vs baseline: 1.2899x; 1.1150x over previous
#include <cuda_runtime.h>
#include <cuda_fp16.h>
#include <cstdint>

namespace {

constexpr int H = 128, W = 128, D = 128;
constexpr int N = H * W * D;          // 2^21
constexpr int B = 2;

// brick / tile geometry: one big brick per 1024-thread CTA
constexpr int BX = 16, BY = 16, BZ = 64;        // voxels per block (16384)
constexpr int HXY = 8;                          // x/y halo
constexpr int HZ = 16;                          // z halo (16-aligned)
constexpr int TX = BX + 2 * HXY + 1;            // 33
constexpr int TY = BY + 2 * HXY + 1;            // 33
constexpr int TZ = 104;                         // 97 needed; 208B rows (16B mult)
constexpr int NROWS = TX * TY;                  // 1089
constexpr int TILE_BYTES = NROWS * TZ * 2;      // 226,512
constexpr int SMEM_BYTES = TILE_BYTES + 16;     // + mbarrier

// fp16 copy of the image (staging reads + rare fallback gathers)
__device__ __align__(16) __half g_img16[(size_t)B * N];

// ---------------- prepass: fp32 image -> fp16 copy ----------------
__global__ __launch_bounds__(256) void pack16_kernel(const float* __restrict__ img) {
    int t = blockIdx.x * blockDim.x + threadIdx.x;
    int base = t * 8;
    float4 a = *reinterpret_cast<const float4*>(img + base);
    float4 c = *reinterpret_cast<const float4*>(img + base + 4);
    __half2 h[4];
    h[0] = __floats2half2_rn(a.x, a.y);
    h[1] = __floats2half2_rn(a.z, a.w);
    h[2] = __floats2half2_rn(c.x, c.y);
    h[3] = __floats2half2_rn(c.z, c.w);
    *reinterpret_cast<uint4*>(g_img16 + base) = *reinterpret_cast<uint4*>(h);
}

// rare fallback: fully masked trilinear gather from global fp16 image
__device__ __noinline__ float sample_masked(const __half* __restrict__ img,
                                            float tx, float ty, float tz,
                                            int x0, int y0, int z0) {
    int x1 = x0 + 1, y1 = y0 + 1, z1 = z0 + 1;
    float wx0 = ((unsigned)x0 < (unsigned)H) ? (1.0f - tx) : 0.0f;
    float wx1 = ((unsigned)x1 < (unsigned)H) ? tx          : 0.0f;
    float wy0 = ((unsigned)y0 < (unsigned)W) ? (1.0f - ty) : 0.0f;
    float wy1 = ((unsigned)y1 < (unsigned)W) ? ty          : 0.0f;
    float wz0 = ((unsigned)z0 < (unsigned)D) ? (1.0f - tz) : 0.0f;
    float wz1 = ((unsigned)z1 < (unsigned)D) ? tz          : 0.0f;
    int cx0 = min(max(x0, 0), H - 1), cx1 = min(max(x1, 0), H - 1);
    int cy0 = min(max(y0, 0), W - 1), cy1 = min(max(y1, 0), W - 1);
    int cz0 = min(max(z0, 0), D - 1), cz1 = min(max(z1, 0), D - 1);
    int bx0 = cx0 * (W * D), bx1 = cx1 * (W * D);
    int by0 = cy0 * D,       by1 = cy1 * D;
    float v000 = __half2float(__ldg(img + bx0 + by0 + cz0));
    float v001 = __half2float(__ldg(img + bx0 + by0 + cz1));
    float v010 = __half2float(__ldg(img + bx0 + by1 + cz0));
    float v011 = __half2float(__ldg(img + bx0 + by1 + cz1));
    float v100 = __half2float(__ldg(img + bx1 + by0 + cz0));
    float v101 = __half2float(__ldg(img + bx1 + by0 + cz1));
    float v110 = __half2float(__ldg(img + bx1 + by1 + cz0));
    float v111 = __half2float(__ldg(img + bx1 + by1 + cz1));
    float c00 = fmaf(wz0, v000, wz1 * v001);
    float c01 = fmaf(wz0, v010, wz1 * v011);
    float c10 = fmaf(wz0, v100, wz1 * v101);
    float c11 = fmaf(wz0, v110, wz1 * v111);
    float d0 = fmaf(wy0, c00, wy1 * c01);
    float d1 = fmaf(wy0, c10, wy1 * c11);
    return fmaf(wx0, d0, wx1 * d1);
}

__device__ __forceinline__ void bulk_cp(unsigned int dst_smem, const void* src,
                                        unsigned int bytes, unsigned int mbar) {
    asm volatile(
        "cp.async.bulk.shared::cluster.global.mbarrier::complete_tx::bytes "
        "[%0], [%1], %2, [%3];\n"
        :: "r"(dst_smem), "l"(src), "r"(bytes), "r"(mbar) : "memory");
}

// ---------------- main kernel: one 16x16x64 brick per 1024-thread block ----------------
__global__ __launch_bounds__(1024, 1) void warp_kernel(const float* __restrict__ ddf,
                                                       float* __restrict__ out) {
    extern __shared__ __half tile[];   // [TX=33][TY=33][TZ=104], mbarrier after

    int bid = blockIdx.x;
    int bz = bid & 1;
    int by = (bid >> 1) & 7;
    int bx = (bid >> 4) & 7;
    int b  = bid >> 7;

    int X0 = bx * BX, Y0 = by * BY, Z0 = bz * BZ;
    int gx0 = X0 - HXY, gy0 = Y0 - HXY, gz0 = Z0 - HZ;   // gz0 multiple of 16

    const __half* img = g_img16 + (size_t)b * N;
    int tid = threadIdx.x;
    int warp = tid >> 5, lane = tid & 31;

    unsigned int tbase = (unsigned int)__cvta_generic_to_shared(tile);
    unsigned int mbar = tbase + (unsigned int)TILE_BYTES;

    // in-bounds z range for every row (gz0, bounds all multiples of 16)
    int zlo = max(gz0, 0), zhi = min(gz0 + TZ, D);
    int zbytes = (zhi - zlo) * 2;                       // multiple of 16
    int zdst0 = (zlo - gz0) * 2;                        // front pad bytes (mult of 16)

    // ---- init mbarrier + expect_tx (thread 0) ----
    if (tid == 0) {
        asm volatile("mbarrier.init.shared.b64 [%0], %1;" :: "r"(mbar), "r"(1u) : "memory");
    }
    __syncthreads();
    if (tid == 0) {
        int ilo = max(0, -gx0), ihi = min(TX, H - gx0);
        int jlo = max(0, -gy0), jhi = min(TY, W - gy0);
        unsigned int tx_total = (unsigned int)((ihi - ilo) * (jhi - jlo)) * (unsigned int)zbytes;
        asm volatile("mbarrier.arrive.expect_tx.shared.b64 _, [%0], %1;"
                     :: "r"(mbar), "r"(tx_total) : "memory");
    }
    __syncthreads();

    // ---- stage: one bulk copy per valid (x,y) row; zero-fill pads / OOB rows ----
    {
        const uint4 zero4 = make_uint4(0, 0, 0, 0);
        #pragma unroll
        for (int pass = 0; pass < 2; pass++) {
            int row = tid + pass * 1024;
            if (row < NROWS) {
                unsigned i = (unsigned)row / (unsigned)TY;
                unsigned j = (unsigned)row - i * TY;
                int gx = gx0 + (int)i, gy = gy0 + (int)j;
                unsigned int drow = tbase + (unsigned int)(row * TZ) * 2u;
                uint4* drow_g = reinterpret_cast<uint4*>(tile + row * TZ);
                if (((unsigned)gx < (unsigned)H) & ((unsigned)gy < (unsigned)W)) {
                    const void* src = img + (((gx << 7) | gy) << 7) + zlo;
                    bulk_cp(drow + (unsigned int)zdst0, src, (unsigned int)zbytes, mbar);
                    for (int o = 0; o < zdst0; o += 16) drow_g[o >> 4] = zero4;
                    for (int o = zdst0 + zbytes; o < TZ * 2; o += 16) drow_g[o >> 4] = zero4;
                } else {
                    #pragma unroll
                    for (int o = 0; o < TZ * 2 / 16; o++) drow_g[o] = zero4;
                }
            }
        }
    }

    // ---- wait for all bulk copies (tx-count) ----
    {
        unsigned int done = 0;
        while (!done) {
            asm volatile(
                "{\n\t.reg .pred P1;\n\t"
                "mbarrier.try_wait.parity.shared.b64 P1, [%1], %2, 0x989680;\n\t"
                "selp.b32 %0, 1, 0, P1;\n\t}"
                : "=r"(done) : "r"(mbar), "r"(0u) : "memory");
        }
    }
    __syncthreads();
    // no further barriers: warps proceed independently

    // ---- compute: warp = (xl, z-half); 16 iters over y; DEPTH-4 ddf prefetch ----
    const float* dbase0 = ddf + (size_t)b * 3 * N;
    float* outb = out + (size_t)b * N;

    int xl = warp >> 1, zh = warp & 1;
    int x = X0 + xl;
    int z = Z0 + zh * 32 + lane;
    int rcur = ((x << 7 | Y0) << 7) | z;
    constexpr int RSTEP = 1 << 7;                      // y += 1 per iteration
    constexpr int DEPTH = 4;

    float pdx[DEPTH], pdy[DEPTH], pdz[DEPTH];
    {
        const float* p = dbase0 + rcur;
        #pragma unroll
        for (int k = 0; k < DEPTH; k++) {
            pdx[k] = __ldg(p);
            pdy[k] = __ldg(p + N);
            pdz[k] = __ldg(p + 2 * N);
            p += RSTEP;
        }
    }
    const float* pnext = dbase0 + rcur + DEPTH * RSTEP;

    int y = Y0;

    #pragma unroll
    for (int it = 0; it < 16; it++) {
        float cdx = pdx[it & 3], cdy = pdy[it & 3], cdz = pdz[it & 3];
        if (it < 16 - DEPTH) {                          // refill slot (it+4)
            pdx[it & 3] = __ldg(pnext);
            pdy[it & 3] = __ldg(pnext + N);
            pdz[it & 3] = __ldg(pnext + 2 * N);
            pnext += RSTEP;
        }

        float fx = (float)x + cdx;
        float fy = (float)y + cdy;
        float fz = (float)z + cdz;

        float x0f = floorf(fx), y0f = floorf(fy), z0f = floorf(fz);
        float tx = fx - x0f, ty = fy - y0f, tz = fz - z0f;
        int x0 = (int)x0f, y0 = (int)y0f, z0 = (int)z0f;

        int x0l = x0 - gx0, y0l = y0 - gy0, z0l = z0 - gz0;
        bool bad = ((unsigned)x0l > (unsigned)(TX - 2)) |
                   ((unsigned)y0l > (unsigned)(TY - 2)) |
                   ((unsigned)z0l > (unsigned)(TZ - 2));

        float res;
        if (!bad) {
            // zeros-padding baked into the staged tile: unmasked 8-tap trilerp
            int base = (x0l * TY + y0l) * TZ + z0l;
            float v000 = __half2float(tile[base]);
            float v001 = __half2float(tile[base + 1]);
            float v010 = __half2float(tile[base + TZ]);
            float v011 = __half2float(tile[base + TZ + 1]);
            float v100 = __half2float(tile[base + TY * TZ]);
            float v101 = __half2float(tile[base + TY * TZ + 1]);
            float v110 = __half2float(tile[base + TY * TZ + TZ]);
            float v111 = __half2float(tile[base + TY * TZ + TZ + 1]);
            float c00 = fmaf(1.0f - tz, v000, tz * v001);
            float c01 = fmaf(1.0f - tz, v010, tz * v011);
            float c10 = fmaf(1.0f - tz, v100, tz * v101);
            float c11 = fmaf(1.0f - tz, v110, tz * v111);
            float d0 = fmaf(1.0f - ty, c00, ty * c01);
            float d1 = fmaf(1.0f - ty, c10, ty * c11);
            res = fmaf(1.0f - tx, d0, tx * d1);
        } else {
            res = sample_masked(img, tx, ty, tz, x0, y0, z0);
        }
        outb[rcur] = res;
        rcur += RSTEP;
        y += 1;
    }
}

} // namespace

extern "C" void kernel_launch(void* const* d_in, const int* in_sizes, int n_in,
                              void* d_out, int out_size) {
    const float* image = (const float*)d_in[0];  // (B, 1, H, W, D) fp32
    const float* ddf   = (const float*)d_in[1];  // (B, 3, H, W, D) fp32
    float* out         = (float*)d_out;          // (B, 1, H, W, D) fp32

    static bool attr_set = false;
    if (!attr_set) {
        cudaFuncSetAttribute(warp_kernel, cudaFuncAttributeMaxDynamicSharedMemorySize,
                             SMEM_BYTES);
        attr_set = true;
    }

    int pack_threads = (B * N) / 8;              // 524,288
    pack16_kernel<<<pack_threads / 256, 256>>>(image);

    int bricks = B * (H / BX) * (W / BY) * (D / BZ);   // 256
    warp_kernel<<<bricks, 1024, SMEM_BYTES>>>(ddf, out);
}